// round 15
// baseline (speedup 1.0000x reference)
#include <cuda_runtime.h>
#include <math.h>
#include <stdint.h>
#include <stddef.h>

#define BB 16
#define CC 200
#define TCI 1000
#define TT 6000
#define HH 200
#define G4 800
#define HIDN 100
#define ROWS (TT*BB)   // 96000

// ---------------- device scratch (no runtime allocations allowed) ----------------
__device__ float g_wt[30 * CC * CC];                    // conv weights [k][ci][co]
__device__ float g_yact[(size_t)BB * CC * TT];          // GELU(convT) [b][c][t]
__device__ float g_xin[(size_t)ROWS * CC];              // lstm1 inputs [t*B+b][c]
__device__ float g_zbuf[(size_t)ROWS * G4];             // gate pre-acts [t*B+b][800]
__device__ float g_h1[(size_t)(TT + 1) * BB * HH];      // layer1 h, rows 0..6000
__device__ float g_h2[(size_t)(TT + 1) * BB * HH];      // layer2 h
__device__ float g_hid[(size_t)ROWS * HIDN];            // mlp hidden
__device__ float g_tmp[(size_t)ROWS * CC];              // mlp out [t*B+b][f]
__device__ float g_a[CC], g_d[CC];                      // BN fold: x_hat = a*y + d

// ---------------- helpers ----------------
__device__ __forceinline__ uint32_t smem_u32(const void* p) {
    uint32_t a;
    asm("{ .reg .u64 t; cvta.to.shared.u64 t, %1; cvt.u32.u64 %0, t; }"
        : "=r"(a) : "l"(p));
    return a;
}
__device__ __forceinline__ float sig_fast(float x) {
    return __fdividef(1.f, 1.f + __expf(-x));
}
__device__ __forceinline__ float tanh_fast(float x) {
    return fmaf(2.f, sig_fast(2.f * x), -1.f);
}

// ---------------- conv weight transpose [ci][co][k] -> [k][ci][co] ----------------
__global__ void k_wt(const float* __restrict__ conv_w) {
    int e = blockIdx.x * 256 + threadIdx.x;
    if (e >= 30 * CC * CC) return;
    int k = e / (CC * CC);
    int rem = e % (CC * CC);
    int ci = rem / CC, co = rem % CC;
    g_wt[e] = conv_w[(ci * CC + co) * 30 + k];
}

// ---------------- ConvTranspose1d (K=30, s=6, p=12) + exact GELU ----------------
__global__ void k_conv(const float* __restrict__ x, const float* __restrict__ conv_b) {
    __shared__ float xs[CC][14];
    int t0 = blockIdx.x * 60;
    int b = blockIdx.y;
    int tcbase = t0 / 6 - 2;
    int tid = threadIdx.x;
    for (int idx = tid; idx < CC * 14; idx += 256) {
        int ci = idx / 14, q = idx % 14;
        int tc = tcbase + q;
        xs[ci][q] = (tc >= 0 && tc < TCI) ? x[(size_t)(b * CC + ci) * TCI + tc] : 0.f;
    }
    __syncthreads();
    int co = tid;
    if (co >= CC) return;
    float acc[60];
    float bias = conv_b[co];
#pragma unroll
    for (int i = 0; i < 60; i++) acc[i] = bias;
    for (int ci = 0; ci < CC; ci++) {
        float xr[14];
#pragma unroll
        for (int q = 0; q < 14; q++) xr[q] = xs[ci][q];
        const float* wp = g_wt + ci * CC + co;
#pragma unroll
        for (int k = 0; k < 30; k++) {
            float wv = wp[(size_t)k * CC * CC];
            int kd = k / 6, km = k % 6;
#pragma unroll
            for (int s = 0; s < 10; s++)
                acc[km + 6 * s] = fmaf(wv, xr[4 + s - kd], acc[km + 6 * s]);
        }
    }
    float* yp = g_yact + ((size_t)(b * CC + co)) * TT + t0;
#pragma unroll
    for (int i = 0; i < 60; i++) {
        float v = acc[i];
        yp[i] = 0.5f * v * (1.f + erff(v * 0.70710678118654752f));
    }
}

// ---------------- per-channel BN stats -> fold into (a, d) ----------------
__global__ void k_stats(const float* __restrict__ bn_g, const float* __restrict__ bn_b) {
    __shared__ float rs[256], rq[256];
    int c = blockIdx.x;
    int tid = threadIdx.x;
    float s = 0.f, q = 0.f;
    for (int b = 0; b < BB; b++) {
        const float* p = g_yact + (size_t)(b * CC + c) * TT;
        for (int t = tid; t < TT; t += 256) {
            float v = p[t];
            s += v; q += v * v;
        }
    }
    rs[tid] = s; rq[tid] = q;
    __syncthreads();
    for (int st = 128; st > 0; st >>= 1) {
        if (tid < st) { rs[tid] += rs[tid + st]; rq[tid] += rq[tid + st]; }
        __syncthreads();
    }
    if (tid == 0) {
        float inv = 1.f / (float)(BB * TT);
        float mu = rs[0] * inv;
        float var = rq[0] * inv - mu * mu;
        float a = bn_g[c] * rsqrtf(var + 1e-5f);
        g_a[c] = a;
        g_d[c] = bn_b[c] - mu * a;
    }
}

// ---------------- build LSTM-1 input matrix X[t*B+b][c] (tiled transpose) ----------
__global__ void k_xin(const float* __restrict__ x_meg) {
    __shared__ float tl[32][33];
    int t0 = blockIdx.x * 32, c0 = blockIdx.y * 32, b = blockIdx.z;
    int tx = threadIdx.x, ty = threadIdx.y;  // 32 x 8
    for (int yy = ty; yy < 32; yy += 8) {
        int c = c0 + yy, t = t0 + tx;
        float v = 0.f;
        if (c < CC && t < TT) {
            if (t == 0)
                v = x_meg[(size_t)(b * CC + c) * TT];
            else
                v = g_a[c] * g_yact[(size_t)(b * CC + c) * TT + (t - 1)] + g_d[c];
        }
        tl[yy][tx] = v;
    }
    __syncthreads();
    for (int yy = ty; yy < 32; yy += 8) {
        int t = t0 + yy, c = c0 + tx;
        if (t < TT && c < CC)
            g_xin[((size_t)t * BB + b) * CC + c] = tl[tx][yy];
    }
}

// ---------------- 128x128 SGEMM-TN: C[M,N] = A[M,K]*B[N,K]^T + bias1(+bias2) ------
// mode: 1 z1 (A=g_xin,  C=g_zbuf), 2 z2 (A=g_h1+3200, C=g_zbuf),
//       3 hid(A=g_h2+3200, C=g_hid, ReLU), 4 out (A=g_hid, C=g_tmp)
__global__ __launch_bounds__(256) void k_gemm(int mode, const float* __restrict__ B,
                                              const float* __restrict__ bias1,
                                              const float* __restrict__ bias2,
                                              int N, int K) {
    const float* A;
    float* C;
    bool relu = false;
    if (mode == 1)      { A = g_xin;        C = g_zbuf; }
    else if (mode == 2) { A = g_h1 + BB*HH; C = g_zbuf; }
    else if (mode == 3) { A = g_h2 + BB*HH; C = g_hid;  relu = true; }
    else                { A = g_hid;        C = g_tmp;  }

    __shared__ float As[8][132];
    __shared__ float Bs[8][132];
    int m0 = blockIdx.x * 128, n0 = blockIdx.y * 128;
    int tid = threadIdx.x;
    int tx = tid & 15, ty = tid >> 4;
    int li = tid >> 1;            // 0..127 tile row for loading
    int lj = (tid & 1) * 4;       // 0 or 4 within k-slab
    float acc[8][8];
#pragma unroll
    for (int u = 0; u < 8; u++)
#pragma unroll
        for (int v = 0; v < 8; v++) acc[u][v] = 0.f;

    for (int k0 = 0; k0 < K; k0 += 8) {
        float4 av = make_float4(0.f, 0.f, 0.f, 0.f);
        if (k0 + lj < K)
            av = *(const float4*)&A[(size_t)(m0 + li) * K + k0 + lj];
        As[lj + 0][li] = av.x; As[lj + 1][li] = av.y;
        As[lj + 2][li] = av.z; As[lj + 3][li] = av.w;
        float4 bv = make_float4(0.f, 0.f, 0.f, 0.f);
        if (n0 + li < N && k0 + lj < K)
            bv = *(const float4*)&B[(size_t)(n0 + li) * K + k0 + lj];
        Bs[lj + 0][li] = bv.x; Bs[lj + 1][li] = bv.y;
        Bs[lj + 2][li] = bv.z; Bs[lj + 3][li] = bv.w;
        __syncthreads();
#pragma unroll
        for (int kk = 0; kk < 8; kk++) {
            float a[8], bb[8];
#pragma unroll
            for (int u = 0; u < 8; u++) a[u] = As[kk][ty * 8 + u];
#pragma unroll
            for (int v = 0; v < 8; v++) bb[v] = Bs[kk][tx * 8 + v];
#pragma unroll
            for (int u = 0; u < 8; u++)
#pragma unroll
                for (int v = 0; v < 8; v++)
                    acc[u][v] = fmaf(a[u], bb[v], acc[u][v]);
        }
        __syncthreads();
    }
#pragma unroll
    for (int v = 0; v < 8; v++) {
        int n = n0 + tx * 8 + v;
        if (n >= N) continue;
        float bbias = bias1[n] + (bias2 ? bias2[n] : 0.f);
#pragma unroll
        for (int u = 0; u < 8; u++) {
            int m = m0 + ty * 8 + u;
            float val = acc[u][v] + bbias;
            if (relu) val = fmaxf(val, 0.f);
            C[(size_t)m * N + n] = val;
        }
    }
}

// ---------------- sequential LSTM sweep: cluster-per-batch, DSMEM h exchange ------
// 128 CTAs, cluster(8): cluster = batch b, rank bs owns hidden units [bs*25, bs*25+25).
// 256 threads: gl = tid/2 (4 gates x 25 units), kh = tid&1 (k half of 100).
// W_hh slice in registers; h double-buffered in smem, broadcast via st.shared::cluster.
__global__ void __cluster_dims__(8, 1, 1) __launch_bounds__(256, 1)
k_sweep(const float* __restrict__ whh, const float* __restrict__ h0l,
        const float* __restrict__ c0l, int layer) {
    __shared__ __align__(16) float h_s[2][HH];
    __shared__ float c_s[25];
    __shared__ float gbuf[100];
    float* hout = layer ? g_h2 : g_h1;

    int tid = threadIdx.x;
    int b = blockIdx.x >> 3;
    uint32_t bs;
    asm("mov.u32 %0, %%cluster_ctarank;" : "=r"(bs));
    int gl = tid >> 1, kh = tid & 1;
    bool act = (gl < 100);

    float w[100];
    if (act) {
        int gt = gl / 25, jl = gl % 25;
        const float* wp = whh + (size_t)(gt * 200 + (int)bs * 25 + jl) * HH + kh * 100;
#pragma unroll
        for (int j = 0; j < 100; j++) w[j] = wp[j];
    } else {
#pragma unroll
        for (int j = 0; j < 100; j++) w[j] = 0.f;
    }
    if (tid < HH) h_s[0][tid] = h0l[tid];
    if (tid < 25) c_s[tid] = c0l[(int)bs * 25 + tid];

    // precompute cluster-mapped addresses of h_s[0][bs*25+tid] in every rank
    uint32_t raddr[8];
    if (tid < 25) {
        uint32_t base0 = smem_u32(&h_s[0][(int)bs * 25 + tid]);
#pragma unroll
        for (int r = 0; r < 8; r++)
            asm("mapa.shared::cluster.u32 %0, %1, %2;"
                : "=r"(raddr[r]) : "r"(base0), "r"(r));
    }
    __syncthreads();
    // one-time: everyone initialized before any cross-CTA traffic
    asm volatile("barrier.cluster.arrive.aligned;" ::: "memory");
    asm volatile("barrier.cluster.wait.aligned;" ::: "memory");

    float z0 = 0.f, z1 = 0.f, z2 = 0.f, z3 = 0.f;
    if (tid < 25) {
        const float* zr = g_zbuf + (size_t)b * G4 + (int)bs * 25 + tid;  // row t=0
        z0 = zr[0]; z1 = zr[200]; z2 = zr[400]; z3 = zr[600];
    }

    for (int t = 0; t < TT; t++) {
        int cur = t & 1;
        uint32_t nxtoff = (uint32_t)((cur ^ 1) * HH * sizeof(float));
        // gate dot: h_t . w_hh_row (float4 smem loads, 4 accumulators)
        const float4* h4 = (const float4*)(&h_s[cur][kh * 100]);
        float p0 = 0.f, p1 = 0.f, p2 = 0.f, p3 = 0.f;
#pragma unroll
        for (int j4 = 0; j4 < 25; j4++) {
            float4 hv = h4[j4];
            p0 = fmaf(w[j4 * 4 + 0], hv.x, p0);
            p1 = fmaf(w[j4 * 4 + 1], hv.y, p1);
            p2 = fmaf(w[j4 * 4 + 2], hv.z, p2);
            p3 = fmaf(w[j4 * 4 + 3], hv.w, p3);
        }
        float p = (p0 + p1) + (p2 + p3);
        p += __shfl_xor_sync(0xffffffffu, p, 1);
        if (!kh && act) gbuf[gl] = p;
        __syncthreads();

        if (tid < 25) {
            float zi = z0 + gbuf[tid];
            float zf = z1 + gbuf[25 + tid];
            float zg = z2 + gbuf[50 + tid];
            float zo = z3 + gbuf[75 + tid];
            float c = sig_fast(zf) * c_s[tid] + sig_fast(zi) * tanh_fast(zg);
            c_s[tid] = c;
            float h = sig_fast(zo) * tanh_fast(c);
            // broadcast h into every rank's next h buffer (incl. self)
#pragma unroll
            for (int r = 0; r < 8; r++)
                asm volatile("st.shared::cluster.f32 [%0], %1;"
                             :: "r"(raddr[r] + nxtoff), "f"(h) : "memory");
            // persist for downstream GEMMs (off critical path)
            hout[(size_t)(t + 1) * (BB * HH) + b * HH + (int)bs * 25 + tid] = h;
            // prefetch next z row
            if (t + 1 < TT) {
                const float* zr = g_zbuf + ((size_t)(t + 1) * BB + b) * G4 + (int)bs * 25 + tid;
                z0 = zr[0]; z1 = zr[200]; z2 = zr[400]; z3 = zr[600];
            }
        }
        // release our DSMEM stores / acquire peers'
        asm volatile("barrier.cluster.arrive.aligned;" ::: "memory");
        asm volatile("barrier.cluster.wait.aligned;" ::: "memory");
    }
}

// ---------------- final transpose: g_tmp[t*B+b][f] -> d_out[b][f][t] ----------------
__global__ void k_tr(float* __restrict__ out) {
    __shared__ float tl[32][33];
    int t0 = blockIdx.x * 32, f0 = blockIdx.y * 32, b = blockIdx.z;
    int tx = threadIdx.x, ty = threadIdx.y;  // 32 x 8
    for (int yy = ty; yy < 32; yy += 8) {
        int t = t0 + yy, f = f0 + tx;
        tl[yy][tx] = (t < TT && f < CC) ? g_tmp[((size_t)t * BB + b) * CC + f] : 0.f;
    }
    __syncthreads();
    for (int yy = ty; yy < 32; yy += 8) {
        int f = f0 + yy, t = t0 + tx;
        if (t < TT && f < CC)
            out[(size_t)(b * CC + f) * TT + t] = tl[tx][yy];
    }
}

// ---------------- host launcher ----------------
extern "C" void kernel_launch(void* const* d_in, const int* in_sizes, int n_in,
                              void* d_out, int out_size) {
    const float* x_fmri = (const float*)d_in[0];
    const float* x_meg  = (const float*)d_in[1];
    const float* conv_w = (const float*)d_in[2];
    const float* conv_b = (const float*)d_in[3];
    const float* bn_g   = (const float*)d_in[4];
    const float* bn_b   = (const float*)d_in[5];
    const float* w_ih0  = (const float*)d_in[6];
    const float* w_hh0  = (const float*)d_in[7];
    const float* b_ih0  = (const float*)d_in[8];
    const float* b_hh0  = (const float*)d_in[9];
    const float* w_ih1  = (const float*)d_in[10];
    const float* w_hh1  = (const float*)d_in[11];
    const float* b_ih1  = (const float*)d_in[12];
    const float* b_hh1  = (const float*)d_in[13];
    const float* out1_w = (const float*)d_in[14];
    const float* out1_b = (const float*)d_in[15];
    const float* out2_w = (const float*)d_in[16];
    const float* out2_b = (const float*)d_in[17];
    const float* h0     = (const float*)d_in[18];
    const float* c0     = (const float*)d_in[19];
    float* out = (float*)d_out;

    k_wt<<<(30 * CC * CC + 255) / 256, 256>>>(conv_w);
    k_conv<<<dim3(TT / 60, BB), 256>>>(x_fmri, conv_b);
    k_stats<<<CC, 256>>>(bn_g, bn_b);
    k_xin<<<dim3(188, 7, BB), dim3(32, 8)>>>(x_meg);

    // z1 = X @ w_ih0^T + b_ih0 + b_hh0
    k_gemm<<<dim3(ROWS / 128, 7), 256>>>(1, w_ih0, b_ih0, b_hh0, G4, CC);
    // layer-1 sweep
    k_sweep<<<128, 256>>>(w_hh0, h0, c0, 0);
    // z2 = H1 @ w_ih1^T + b_ih1 + b_hh1
    k_gemm<<<dim3(ROWS / 128, 7), 256>>>(2, w_ih1, b_ih1, b_hh1, G4, HH);
    // layer-2 sweep
    k_sweep<<<128, 256>>>(w_hh1, h0 + HH, c0 + HH, 1);
    // hid = relu(H2 @ out1_w^T + out1_b)
    k_gemm<<<dim3(ROWS / 128, 1), 256>>>(3, out1_w, out1_b, nullptr, HIDN, HH);
    // out = hid @ out2_w^T + out2_b
    k_gemm<<<dim3(ROWS / 128, 2), 256>>>(4, out2_w, out2_b, nullptr, CC, HIDN);
    // transpose to [b][f][t]
    k_tr<<<dim3(188, 7, BB), dim3(32, 8)>>>(out);
}